// round 12
// baseline (speedup 1.0000x reference)
#include <cuda_runtime.h>
#include <cuda_fp16.h>
#include <stdint.h>
#include <math.h>

// Problem constants
#define B_   4096
#define T_   26
#define IN_  512
#define H_   512
#define NC_  97
#define NE_  256
#define K1_  (IN_ + NE_)   // 768
#define G_   (4 * H_)      // 2048
#define M1_  (B_ * T_)     // 106496

// Pipeline: 3 stages x 2 tiles (A, B) x 16KB = 96KB  -> 2 CTAs/SM
#define TILE_BYTES  16384
#define STAGE_BYTES (2 * TILE_BYTES)
#define NSTAGES     3
#define SMEM_DYN    (NSTAGES * STAGE_BYTES + 128)

// Persistent recurrent kernel decomposition
#define GROUPS      32     // batch m-tiles (4096 / 128)
#define GROUP_CTAS  8      // CTAs per group; each owns 2 n-tiles (64 units)

// ---------------------------------------------------------------------------
// Scratch (device globals: no allocation allowed anywhere)
// ---------------------------------------------------------------------------
// g_gx16 stored fp16, PERMUTED gate order: col n = gate (n&3) of unit (n>>2).
__device__ __half g_gx16[(size_t)M1_ * G_];
__device__ float g_c[B_ * H_];                    // cell state
__device__ __half g_x[(size_t)M1_ * IN_];         // batch_H fp16 (emb factored out)
__device__ __half g_H[(size_t)M1_ * H_];          // hiddens fp16 [b*T+t, H]
__device__ __half g_Wih[G_ * IN_];                // W_ih[:, :512] fp16 (permuted)
__device__ __half g_Whh[G_ * H_];
__device__ __half g_Wg[128 * H_];                 // W_gen padded to 128 rows
__device__ float g_eg[98 * G_];                   // emb@Wih_emb^T + bih (permuted)
__device__ int   g_bar[GROUPS];                   // per-group arrival counters

// ---------------------------------------------------------------------------
// PTX helpers (compute_103-safe: ldmatrix + mma.sync + cp.async)
// ---------------------------------------------------------------------------
__device__ __forceinline__ uint32_t smem_u32(const void* p) {
    uint32_t a;
    asm("{ .reg .u64 t; cvta.to.shared.u64 t, %1; cvt.u32.u64 %0, t; }"
        : "=r"(a) : "l"(p));
    return a;
}

__device__ __forceinline__ void ldmx4(uint32_t* r, uint32_t addr) {
    asm volatile("ldmatrix.sync.aligned.m8n8.x4.shared.b16 {%0,%1,%2,%3}, [%4];"
                 : "=r"(r[0]), "=r"(r[1]), "=r"(r[2]), "=r"(r[3]) : "r"(addr));
}

__device__ __forceinline__ void mma_f16(float* d, const uint32_t* a,
                                        uint32_t b0, uint32_t b1) {
    asm volatile(
        "mma.sync.aligned.m16n8k16.row.col.f32.f16.f16.f32 "
        "{%0,%1,%2,%3}, {%4,%5,%6,%7}, {%8,%9}, {%0,%1,%2,%3};"
        : "+f"(d[0]), "+f"(d[1]), "+f"(d[2]), "+f"(d[3])
        : "r"(a[0]), "r"(a[1]), "r"(a[2]), "r"(a[3]), "r"(b0), "r"(b1));
}

__device__ __forceinline__ void cp16(uint32_t s, const void* g) {
    asm volatile("cp.async.cg.shared.global [%0], [%1], 16;"
                 :: "r"(s), "l"(g) : "memory");
}
__device__ __forceinline__ void cp_commit() {
    asm volatile("cp.async.commit_group;" ::: "memory");
}
template <int N>
__device__ __forceinline__ void cp_wait() {
    asm volatile("cp.async.wait_group %0;" :: "n"(N) : "memory");
}

// ---------------------------------------------------------------------------
// Small prep kernels
// ---------------------------------------------------------------------------
__global__ void zero_state_kernel() {
    int i = blockIdx.x * blockDim.x + threadIdx.x;
    ((float4*)g_c)[i] = make_float4(0.f, 0.f, 0.f, 0.f);
    if (blockIdx.x == 0 && threadIdx.x < GROUPS) g_bar[threadIdx.x] = 0;
}

// batch_H -> fp16.  grid = M1, block = 128
__global__ void convert_x_kernel(const float* __restrict__ bh) {
    int m = blockIdx.x;
    int k = threadIdx.x * 4;
    float4 v = *(const float4*)(bh + (size_t)m * IN_ + k);
    size_t o = (size_t)m * IN_ + k;
    g_x[o]   = __float2half_rn(v.x);
    g_x[o+1] = __float2half_rn(v.y);
    g_x[o+2] = __float2half_rn(v.z);
    g_x[o+3] = __float2half_rn(v.w);
}

// Weight -> fp16.  which: 0=Wih[:, :512] 1=Whh (both gate-permuted) 2=Wgen
__global__ void convert_w_kernel(const float* __restrict__ src, int which,
                                 int Rvalid, int Ksrc) {
    int r = blockIdx.x;                       // destination row
    int k = threadIdx.x * 4;                  // 0..508 (Kdst = 512)
    int sr = (which < 2) ? ((r & 3) * H_ + (r >> 2)) : r;   // gate permutation
    float4 v = make_float4(0.f, 0.f, 0.f, 0.f);
    if (sr < Rvalid) v = *(const float4*)(src + (size_t)sr * Ksrc + k);
    __half* dst = (which == 0) ? g_Wih : (which == 1) ? g_Whh : g_Wg;
    size_t o = (size_t)r * IN_ + k;
    dst[o]   = __float2half_rn(v.x);
    dst[o+1] = __float2half_rn(v.y);
    dst[o+2] = __float2half_rn(v.z);
    dst[o+3] = __float2half_rn(v.w);
}

// eg[c][n] = emb_table[c] . W_ih[perm(n), 512:768] + b_ih[perm(n)]   (fp32)
// grid = 98, block = 256
__global__ void emb_gates_kernel(const float* __restrict__ emb,
                                 const float* __restrict__ Wih,
                                 const float* __restrict__ bih) {
    __shared__ float se[NE_];
    int c = blockIdx.x;
    for (int i = threadIdx.x; i < NE_; i += 256)
        se[i] = emb[(size_t)c * NE_ + i];
    __syncthreads();
    for (int n = threadIdx.x; n < G_; n += 256) {
        int sr = (n & 3) * H_ + (n >> 2);
        const float* w = Wih + (size_t)sr * K1_ + IN_;
        float s = bih[sr];
#pragma unroll 8
        for (int k = 0; k < NE_; k++) s = fmaf(se[k], w[k], s);
        g_eg[c * G_ + n] = s;
    }
}

// ---------------------------------------------------------------------------
// fp16 GEMM via mma.sync, 3-stage cp.async pipeline, occ 2.
// mode 0: gx    = batch_H @ Wih[:, :512]^T (perm), K=512
//                 epilogue += eg[text[m]][n]  -> g_gx16 fp16
// mode 2: probs = H @ Wgen^T, K=512 -> outp (+bg, n<97)
// 8 warps: warp tile 64(m) x 32(n); K-chunk 64.
// ---------------------------------------------------------------------------
__global__ void __launch_bounds__(256, 2)
mma_gemm_kernel(int mode, const float* __restrict__ bias,
                const int* __restrict__ text, float* __restrict__ outp)
{
    extern __shared__ char dsm[];

    const int tid = threadIdx.x;
    const int wid = tid >> 5;
    const int lid = tid & 31;
    const int wm  = wid & 1;
    const int wn  = wid >> 1;
    const int n0  = blockIdx.x * 128;
    const int m0  = blockIdx.y * 128;

    const __half *A, *Bp;
    if (mode == 0) { A = g_x; Bp = g_Wih; }
    else           { A = g_H; Bp = g_Wg;  }
    const int K = IN_;   // 512 for both modes now

    uint32_t raw  = smem_u32(dsm);
    uint32_t base = (raw + 127) & ~127u;
    uint32_t stg[NSTAGES];
#pragma unroll
    for (int s = 0; s < NSTAGES; s++) stg[s] = base + s * STAGE_BYTES;

    float acc[4][4][4];
#pragma unroll
    for (int mt = 0; mt < 4; mt++)
#pragma unroll
        for (int nt = 0; nt < 4; nt++)
#pragma unroll
            for (int r = 0; r < 4; r++) acc[mt][nt][r] = 0.0f;

    const int a_r  = lid & 15;
    const int a_kh = lid >> 4;
    const int b_r  = (lid & 7) + ((lid & 16) ? 8 : 0);
    const int b_kh = (lid >> 3) & 1;

    const int nchunks = K >> 6;   // 8

    auto load_stage = [&](int ch, uint32_t sb) {
        const int k0 = ch * 64;
#pragma unroll
        for (int i = tid; i < 1024; i += 256) {
            int r = i >> 3, u = i & 7;
            uint32_t sw = (r << 7) + ((u ^ (r & 7)) << 4);
            cp16(sb + sw,              A  + (size_t)(m0 + r) * IN_ + k0 + u * 8);
            cp16(sb + TILE_BYTES + sw, Bp + (size_t)(n0 + r) * IN_ + k0 + u * 8);
        }
    };

#pragma unroll
    for (int s = 0; s < NSTAGES - 1; s++) {
        if (s < nchunks) load_stage(s, stg[s]);
        cp_commit();
    }

    for (int ch = 0; ch < nchunks; ch++) {
        if (ch + NSTAGES - 1 < nchunks)
            load_stage(ch + NSTAGES - 1, stg[(ch + NSTAGES - 1) % NSTAGES]);
        cp_commit();
        cp_wait<NSTAGES - 1>();
        __syncthreads();

        const uint32_t aA = stg[ch % NSTAGES];
        const uint32_t aB = aA + TILE_BYTES;

#pragma unroll
        for (int ks = 0; ks < 4; ks++) {
            uint32_t af[4][4], bf[2][4];
#pragma unroll
            for (int mt = 0; mt < 4; mt++) {
                int row = wm * 64 + mt * 16 + a_r;
                int kb  = ks * 2 + a_kh;
                ldmx4(af[mt], aA + (row << 7) + ((kb ^ (row & 7)) << 4));
            }
#pragma unroll
            for (int p = 0; p < 2; p++) {
                int row = wn * 32 + p * 16 + b_r;
                int kb  = ks * 2 + b_kh;
                ldmx4(bf[p], aB + (row << 7) + ((kb ^ (row & 7)) << 4));
            }
#pragma unroll
            for (int mt = 0; mt < 4; mt++)
#pragma unroll
                for (int nt = 0; nt < 4; nt++) {
                    int p = nt >> 1, o = (nt & 1) * 2;
                    mma_f16(acc[mt][nt], af[mt], bf[p][o], bf[p][o + 1]);
                }
        }
        __syncthreads();
    }

    const int qr = lid >> 2, qc = lid & 3;
#pragma unroll
    for (int mt = 0; mt < 4; mt++)
#pragma unroll
        for (int half = 0; half < 2; half++) {
            int m = m0 + wm * 64 + mt * 16 + qr + half * 8;
            const float* eg = (mode == 0) ? g_eg + (size_t)text[m] * G_ : nullptr;
#pragma unroll
            for (int nt = 0; nt < 4; nt++) {
                int n = n0 + wn * 32 + nt * 8 + qc * 2;
                float v0 = acc[mt][nt][half * 2];
                float v1 = acc[mt][nt][half * 2 + 1];
                if (mode == 2) {
                    if (n < NC_)     outp[(size_t)m * NC_ + n]     = v0 + bias[n];
                    if (n + 1 < NC_) outp[(size_t)m * NC_ + n + 1] = v1 + bias[n + 1];
                } else {
                    // eg already holds permuted emb contribution + bih
                    *(__half2*)(g_gx16 + (size_t)m * G_ + n) =
                        __floats2half2_rn(v0 + eg[n], v1 + eg[n + 1]);
                }
            }
        }
}

// ---------------------------------------------------------------------------
// Persistent recurrent kernel: 256 CTAs = 32 groups x 8.
// Group g owns batch rows [g*128, g*128+128); CTA sub owns n-tiles
// sub*256 and sub*256+128 (64 hidden units).  25 steps with per-group
// atomic barrier (h is batch-local; no global sync needed).
// ---------------------------------------------------------------------------
__global__ void __launch_bounds__(256, 2)
recurrent_kernel(float* __restrict__ out_hid, const float* __restrict__ bhh)
{
    extern __shared__ char dsm[];

    const int tid = threadIdx.x;
    const int wid = tid >> 5;
    const int lid = tid & 31;
    const int wm  = wid & 1;
    const int wn  = wid >> 1;
    const int grp = blockIdx.x >> 3;
    const int sub = blockIdx.x & 7;
    const int m0  = grp * 128;

    uint32_t raw  = smem_u32(dsm);
    uint32_t base = (raw + 127) & ~127u;
    float* stage_f = (float*)(dsm + (base - raw));
    uint32_t stg[NSTAGES];
#pragma unroll
    for (int s = 0; s < NSTAGES; s++) stg[s] = base + s * STAGE_BYTES;

    const int a_r  = lid & 15;
    const int a_kh = lid >> 4;
    const int b_r  = (lid & 7) + ((lid & 16) ? 8 : 0);
    const int b_kh = (lid >> 3) & 1;
    const int qr = lid >> 2, qc = lid & 3;

    for (int t = 1; t < T_; t++) {
        const __half* A = g_H + (size_t)(t - 1) * H_;   // row b -> (b*T+t-1)*H
        const long lda = (long)T_ * H_;

#pragma unroll 1
        for (int tile = 0; tile < 2; tile++) {
            const int n0 = sub * 256 + tile * 128;

            float acc[4][4][4];
#pragma unroll
            for (int mt = 0; mt < 4; mt++)
#pragma unroll
                for (int nt = 0; nt < 4; nt++)
#pragma unroll
                    for (int r = 0; r < 4; r++) acc[mt][nt][r] = 0.0f;

            auto load_stage = [&](int ch, uint32_t sb) {
                const int k0 = ch * 64;
#pragma unroll
                for (int i = tid; i < 1024; i += 256) {
                    int r = i >> 3, u = i & 7;
                    uint32_t sw = (r << 7) + ((u ^ (r & 7)) << 4);
                    cp16(sb + sw,              A + (size_t)(m0 + r) * lda + k0 + u * 8);
                    cp16(sb + TILE_BYTES + sw, g_Whh + (size_t)(n0 + r) * H_ + k0 + u * 8);
                }
            };

            load_stage(0, stg[0]); cp_commit();
            load_stage(1, stg[1]); cp_commit();

            for (int ch = 0; ch < 8; ch++) {   // K = 512 -> 8 chunks
                if (ch + 2 < 8) load_stage(ch + 2, stg[(ch + 2) % NSTAGES]);
                cp_commit();
                cp_wait<2>();
                __syncthreads();

                const uint32_t aA = stg[ch % NSTAGES];
                const uint32_t aB = aA + TILE_BYTES;
#pragma unroll
                for (int ks = 0; ks < 4; ks++) {
                    uint32_t af[4][4], bf[2][4];
#pragma unroll
                    for (int mt = 0; mt < 4; mt++) {
                        int row = wm * 64 + mt * 16 + a_r;
                        int kb  = ks * 2 + a_kh;
                        ldmx4(af[mt], aA + (row << 7) + ((kb ^ (row & 7)) << 4));
                    }
#pragma unroll
                    for (int p = 0; p < 2; p++) {
                        int row = wn * 32 + p * 16 + b_r;
                        int kb  = ks * 2 + b_kh;
                        ldmx4(bf[p], aB + (row << 7) + ((kb ^ (row & 7)) << 4));
                    }
#pragma unroll
                    for (int mt = 0; mt < 4; mt++)
#pragma unroll
                        for (int nt = 0; nt < 4; nt++) {
                            int p = nt >> 1, o = (nt & 1) * 2;
                            mma_f16(acc[mt][nt], af[mt], bf[p][o], bf[p][o + 1]);
                        }
                }
                __syncthreads();
            }
            cp_wait<0>();

            // stage acc -> smem, then fused pointwise for these 32 units
#pragma unroll
            for (int mt = 0; mt < 4; mt++)
#pragma unroll
                for (int nt = 0; nt < 4; nt++)
#pragma unroll
                    for (int half = 0; half < 2; half++) {
                        int r = wm * 64 + mt * 16 + qr + half * 8;
                        int n = wn * 32 + nt * 8 + qc * 2;
                        stage_f[r * 132 + n]     = acc[mt][nt][half * 2];
                        stage_f[r * 132 + n + 1] = acc[mt][nt][half * 2 + 1];
                    }
            __syncthreads();

            const int j0 = n0 >> 2;
#pragma unroll
            for (int i = tid; i < 4096; i += 256) {
                int r  = i >> 5;
                int jj = i & 31;
                int b  = m0 + r;
                int j  = j0 + jj;
                float4 a4 = *(const float4*)&stage_f[r * 132 + jj * 4];
                const __half2* gxp = (const __half2*)(
                    g_gx16 + ((size_t)b * T_ + t) * G_ + n0 + jj * 4);
                float2 gx01 = __half22float2(gxp[0]);
                float2 gx23 = __half22float2(gxp[1]);
                float gi = a4.x + gx01.x + bhh[j];
                float gf = a4.y + gx01.y + bhh[j +     H_];
                float gg = a4.z + gx23.x + bhh[j + 2 * H_];
                float go = a4.w + gx23.y + bhh[j + 3 * H_];

                float i_ = 1.0f / (1.0f + expf(-gi));
                float f_ = 1.0f / (1.0f + expf(-gf));
                float g_ = tanhf(gg);
                float o_ = 1.0f / (1.0f + expf(-go));

                int idx = b * H_ + j;
                float c = f_ * g_c[idx] + i_ * g_;
                float h = o_ * tanhf(c);
                g_c[idx] = c;

                size_t oo = ((size_t)b * T_ + t) * H_ + j;
                out_hid[oo] = h;
                g_H[oo]     = __float2half_rn(h);
            }
            __syncthreads();   // stage_f free before next tile's loads
        }

        // ---- group barrier: wait for all 8 CTAs of this group ----
        if (tid == 0) {
            __threadfence();
            atomicAdd(&g_bar[grp], 1);
            while (*(volatile int*)&g_bar[grp] < GROUP_CTAS * t)
                __nanosleep(64);
            __threadfence();
        }
        __syncthreads();
    }
}

// ---------------------------------------------------------------------------
// t = 0 step: h = 0, so gates = gx (permuted fp16, includes eg+bih) + bhh
// ---------------------------------------------------------------------------
__global__ void lstm_t0(float* __restrict__ out_hid, const float* __restrict__ bhh)
{
    int i = blockIdx.x * blockDim.x + threadIdx.x;   // B*H
    int b = i >> 9;
    int j = i & 511;

    const __half2* gxp = (const __half2*)(g_gx16 + (size_t)b * T_ * G_ + 4 * j);
    float2 g01 = __half22float2(gxp[0]);
    float2 g23 = __half22float2(gxp[1]);
    float gi = g01.x + bhh[j];
    float gf = g01.y + bhh[j +     H_];
    float gg = g23.x + bhh[j + 2 * H_];
    float go = g23.y + bhh[j + 3 * H_];

    float i_ = 1.0f / (1.0f + expf(-gi));
    float f_ = 1.0f / (1.0f + expf(-gf));
    float g_ = tanhf(gg);
    float o_ = 1.0f / (1.0f + expf(-go));

    float c = i_ * g_;          // c_prev = 0
    float h = o_ * tanhf(c);
    g_c[i] = c;

    size_t o = (size_t)b * T_ * H_ + j;   // t = 0
    out_hid[o] = h;
    g_H[o] = __float2half_rn(h);
}

// ---------------------------------------------------------------------------
// Launch: zero -> converts/eg -> gx GEMM (K=512) -> t0 -> persistent -> probs
// d_out = [probs (B*T*97) | output_hiddens (B*T*512)]
// ---------------------------------------------------------------------------
extern "C" void kernel_launch(void* const* d_in, const int* in_sizes, int n_in,
                              void* d_out, int out_size)
{
    const float* bh   = (const float*)d_in[0];
    const int*   text = (const int*)  d_in[1];
    const float* emb  = (const float*)d_in[2];
    const float* Wih  = (const float*)d_in[3];
    const float* Whh  = (const float*)d_in[4];
    const float* bih  = (const float*)d_in[5];
    const float* bhh  = (const float*)d_in[6];
    const float* Wg   = (const float*)d_in[7];
    const float* bg   = (const float*)d_in[8];

    float* probs = (float*)d_out;                     // [M1, 97]
    float* hid   = probs + (size_t)M1_ * NC_;         // [M1, 512]

    (void)in_sizes; (void)n_in; (void)out_size;

    cudaFuncSetAttribute((const void*)mma_gemm_kernel,
                         cudaFuncAttributeMaxDynamicSharedMemorySize, SMEM_DYN);
    cudaFuncSetAttribute((const void*)recurrent_kernel,
                         cudaFuncAttributeMaxDynamicSharedMemorySize, SMEM_DYN);

    zero_state_kernel<<<(B_ * H_ / 4) / 256, 256>>>();
    convert_x_kernel<<<M1_, IN_ / 4>>>(bh);
    convert_w_kernel<<<G_,  IN_ / 4>>>(Wih, 0, G_,  K1_);   // first 512 cols
    convert_w_kernel<<<G_,  IN_ / 4>>>(Whh, 1, G_,  H_);
    convert_w_kernel<<<128, IN_ / 4>>>(Wg,  2, NC_, H_);
    emb_gates_kernel<<<98, 256>>>(emb, Wih, bih);

    // gx: M=106496 x N=2048, K=512.  n-tiles fastest => A tile L2-resident.
    mma_gemm_kernel<<<dim3(16, 832), 256, SMEM_DYN>>>(0, nullptr, text, nullptr);

    lstm_t0<<<(B_ * H_) / 256, 256>>>(hid, bhh);

    recurrent_kernel<<<GROUPS * GROUP_CTAS, 256, SMEM_DYN>>>(hid, bhh);

    // probs: N=97 padded to one 128-tile
    mma_gemm_kernel<<<dim3(1, 832), 256, SMEM_DYN>>>(2, bg, nullptr, probs);
}

// round 13
// speedup vs baseline: 1.0558x; 1.0558x over previous
#include <cuda_runtime.h>
#include <cuda_fp16.h>
#include <stdint.h>
#include <math.h>

// Problem constants
#define B_   4096
#define T_   26
#define IN_  512
#define H_   512
#define NC_  97
#define NE_  256
#define K1_  (IN_ + NE_)   // 768  (x = concat(batch_H, emb))
#define KC_  (H_ + K1_)    // 1280 (combined [h | x] contraction)
#define G_   (4 * H_)      // 2048
#define M1_  (B_ * T_)     // 106496

// Pipeline: 3 stages x 2 tiles (A, B) x 16KB = 96KB  -> 2 CTAs/SM
#define TILE_BYTES  16384
#define STAGE_BYTES (2 * TILE_BYTES)
#define NSTAGES     3
#define SMEM_DYN    (NSTAGES * STAGE_BYTES + 128)

// Persistent recurrent kernel decomposition
#define GROUPS      32     // batch m-tiles (4096 / 128)
#define GROUP_CTAS  8      // CTAs per group; each owns 2 n-tiles (64 units)

// ---------------------------------------------------------------------------
// Scratch (device globals: no allocation allowed anywhere)
// ---------------------------------------------------------------------------
__device__ float g_c[B_ * H_];                    // cell state
__device__ __half g_x[(size_t)M1_ * K1_];         // concat(batch_H, emb) fp16
__device__ __half g_H[(size_t)M1_ * H_];          // hiddens fp16 [b*T+t, H]
__device__ __half g_W[G_ * KC_];                  // [Whh | Wih] fp16, gate-permuted rows
__device__ __half g_Wg[128 * H_];                 // W_gen padded to 128 rows
__device__ float g_bias[G_];                      // bih+bhh, PERMUTED gate order
__device__ int   g_bar[GROUPS];                   // per-group arrival counters

// ---------------------------------------------------------------------------
// PTX helpers (compute_103-safe: ldmatrix + mma.sync + cp.async)
// ---------------------------------------------------------------------------
__device__ __forceinline__ uint32_t smem_u32(const void* p) {
    uint32_t a;
    asm("{ .reg .u64 t; cvta.to.shared.u64 t, %1; cvt.u32.u64 %0, t; }"
        : "=r"(a) : "l"(p));
    return a;
}

__device__ __forceinline__ void ldmx4(uint32_t* r, uint32_t addr) {
    asm volatile("ldmatrix.sync.aligned.m8n8.x4.shared.b16 {%0,%1,%2,%3}, [%4];"
                 : "=r"(r[0]), "=r"(r[1]), "=r"(r[2]), "=r"(r[3]) : "r"(addr));
}

__device__ __forceinline__ void mma_f16(float* d, const uint32_t* a,
                                        uint32_t b0, uint32_t b1) {
    asm volatile(
        "mma.sync.aligned.m16n8k16.row.col.f32.f16.f16.f32 "
        "{%0,%1,%2,%3}, {%4,%5,%6,%7}, {%8,%9}, {%0,%1,%2,%3};"
        : "+f"(d[0]), "+f"(d[1]), "+f"(d[2]), "+f"(d[3])
        : "r"(a[0]), "r"(a[1]), "r"(a[2]), "r"(a[3]), "r"(b0), "r"(b1));
}

__device__ __forceinline__ void cp16(uint32_t s, const void* g) {
    asm volatile("cp.async.cg.shared.global [%0], [%1], 16;"
                 :: "r"(s), "l"(g) : "memory");
}
__device__ __forceinline__ void cp_commit() {
    asm volatile("cp.async.commit_group;" ::: "memory");
}
template <int N>
__device__ __forceinline__ void cp_wait() {
    asm volatile("cp.async.wait_group %0;" :: "n"(N) : "memory");
}

// ---------------------------------------------------------------------------
// Small prep kernels
// ---------------------------------------------------------------------------
__global__ void zero_state_kernel() {
    int i = blockIdx.x * blockDim.x + threadIdx.x;
    ((float4*)g_c)[i] = make_float4(0.f, 0.f, 0.f, 0.f);
    if (blockIdx.x == 0 && threadIdx.x < GROUPS) g_bar[threadIdx.x] = 0;
}

// x = concat(batch_H, emb[text]) -> fp16.  grid = M1, block = 192
__global__ void convert_x_kernel(const float* __restrict__ bh,
                                 const int* __restrict__ text,
                                 const float* __restrict__ emb) {
    int m = blockIdx.x;
    int k = threadIdx.x * 4;
    float4 v;
    if (k < IN_) v = *(const float4*)(bh + (size_t)m * IN_ + k);
    else         v = *(const float4*)(emb + (size_t)text[m] * NE_ + (k - IN_));
    size_t o = (size_t)m * K1_ + k;
    g_x[o]   = __float2half_rn(v.x);
    g_x[o+1] = __float2half_rn(v.y);
    g_x[o+2] = __float2half_rn(v.z);
    g_x[o+3] = __float2half_rn(v.w);
}

// Combined weight [Whh | Wih], gate-permuted rows -> fp16.  grid = G_, block = 320
__global__ void convert_w_kernel(const float* __restrict__ Whh,
                                 const float* __restrict__ Wih) {
    int r = blockIdx.x;
    int k = threadIdx.x * 4;                  // 0..1276
    int sr = (r & 3) * H_ + (r >> 2);         // gate permutation
    float4 v;
    if (k < H_) v = *(const float4*)(Whh + (size_t)sr * H_ + k);
    else        v = *(const float4*)(Wih + (size_t)sr * K1_ + (k - H_));
    size_t o = (size_t)r * KC_ + k;
    g_W[o]   = __float2half_rn(v.x);
    g_W[o+1] = __float2half_rn(v.y);
    g_W[o+2] = __float2half_rn(v.z);
    g_W[o+3] = __float2half_rn(v.w);
}

// W_gen (padded to 128 rows) -> fp16.  grid = 128, block = 128
__global__ void convert_wg_kernel(const float* __restrict__ Wg) {
    int r = blockIdx.x;
    int k = threadIdx.x * 4;
    float4 v = make_float4(0.f, 0.f, 0.f, 0.f);
    if (r < NC_) v = *(const float4*)(Wg + (size_t)r * H_ + k);
    size_t o = (size_t)r * H_ + k;
    g_Wg[o]   = __float2half_rn(v.x);
    g_Wg[o+1] = __float2half_rn(v.y);
    g_Wg[o+2] = __float2half_rn(v.z);
    g_Wg[o+3] = __float2half_rn(v.w);
}

// g_bias[n] = bih[perm(n)] + bhh[perm(n)]  (permuted).  grid = 8, block = 256
__global__ void bias_kernel(const float* __restrict__ bih,
                            const float* __restrict__ bhh) {
    int n = blockIdx.x * blockDim.x + threadIdx.x;
    int sr = (n & 3) * H_ + (n >> 2);
    g_bias[n] = bih[sr] + bhh[sr];
}

// ---------------------------------------------------------------------------
// Persistent recurrent kernel: 256 CTAs = 32 groups x 8.
// Group g owns batch rows [g*128, g*128+128); CTA sub owns 2 n-tiles.
// Steps t=0..25; gates_t = [h_{t-1} | x_t] @ [Whh | Wih]^T, K=1280.
// t=0 starts at chunk 8 (h=0).  Per-group atomic barrier between steps.
// ---------------------------------------------------------------------------
__global__ void __launch_bounds__(256, 2)
recurrent_kernel(float* __restrict__ out_hid)
{
    extern __shared__ char dsm[];

    const int tid = threadIdx.x;
    const int wid = tid >> 5;
    const int lid = tid & 31;
    const int wm  = wid & 1;
    const int wn  = wid >> 1;
    const int grp = blockIdx.x >> 3;
    const int sub = blockIdx.x & 7;
    const int m0  = grp * 128;

    uint32_t raw  = smem_u32(dsm);
    uint32_t base = (raw + 127) & ~127u;
    float* stage_f = (float*)(dsm + (base - raw));
    uint32_t stg[NSTAGES];
#pragma unroll
    for (int s = 0; s < NSTAGES; s++) stg[s] = base + s * STAGE_BYTES;

    const int a_r  = lid & 15;
    const int a_kh = lid >> 4;
    const int b_r  = (lid & 7) + ((lid & 16) ? 8 : 0);
    const int b_kh = (lid >> 3) & 1;
    const int qr = lid >> 2, qc = lid & 3;

    for (int t = 0; t < T_; t++) {
        const __half* Ah = g_H + (size_t)(t - 1) * H_;  // row b -> (b*T+t-1)*H
        const __half* Ax = g_x + (size_t)t * K1_;       // row b -> (b*T+t)*K1
        const int start = (t == 0) ? 8 : 0;             // t=0: h part is zero

#pragma unroll 1
        for (int tile = 0; tile < 2; tile++) {
            const int n0 = sub * 256 + tile * 128;

            float acc[4][4][4];
#pragma unroll
            for (int mt = 0; mt < 4; mt++)
#pragma unroll
                for (int nt = 0; nt < 4; nt++)
#pragma unroll
                    for (int r = 0; r < 4; r++) acc[mt][nt][r] = 0.0f;

            // chunk ch: 0..7 -> h(t-1), 8..19 -> x(t)
            auto load_stage = [&](int ch, uint32_t sb) {
#pragma unroll
                for (int i = tid; i < 1024; i += 256) {
                    int r = i >> 3, u = i & 7;
                    uint32_t sw = (r << 7) + ((u ^ (r & 7)) << 4);
                    const __half* src = (ch < 8)
                        ? Ah + ((size_t)(m0 + r) * T_) * H_ + ch * 64 + u * 8
                        : Ax + ((size_t)(m0 + r) * T_) * K1_ + (ch - 8) * 64 + u * 8;
                    cp16(sb + sw, src);
                    cp16(sb + TILE_BYTES + sw,
                         g_W + (size_t)(n0 + r) * KC_ + ch * 64 + u * 8);
                }
            };

            load_stage(start, stg[start % NSTAGES]);     cp_commit();
            load_stage(start + 1, stg[(start + 1) % NSTAGES]); cp_commit();

            for (int ch = start; ch < 20; ch++) {
                if (ch + 2 < 20) load_stage(ch + 2, stg[(ch + 2) % NSTAGES]);
                cp_commit();
                cp_wait<2>();
                __syncthreads();

                const uint32_t aA = stg[ch % NSTAGES];
                const uint32_t aB = aA + TILE_BYTES;
#pragma unroll
                for (int ks = 0; ks < 4; ks++) {
                    uint32_t af[4][4], bf[2][4];
#pragma unroll
                    for (int mt = 0; mt < 4; mt++) {
                        int row = wm * 64 + mt * 16 + a_r;
                        int kb  = ks * 2 + a_kh;
                        ldmx4(af[mt], aA + (row << 7) + ((kb ^ (row & 7)) << 4));
                    }
#pragma unroll
                    for (int p = 0; p < 2; p++) {
                        int row = wn * 32 + p * 16 + b_r;
                        int kb  = ks * 2 + b_kh;
                        ldmx4(bf[p], aB + (row << 7) + ((kb ^ (row & 7)) << 4));
                    }
#pragma unroll
                    for (int mt = 0; mt < 4; mt++)
#pragma unroll
                        for (int nt = 0; nt < 4; nt++) {
                            int p = nt >> 1, o = (nt & 1) * 2;
                            mma_f16(acc[mt][nt], af[mt], bf[p][o], bf[p][o + 1]);
                        }
                }
                __syncthreads();
            }

            // stage acc -> smem, then fused pointwise for these 32 units
#pragma unroll
            for (int mt = 0; mt < 4; mt++)
#pragma unroll
                for (int nt = 0; nt < 4; nt++)
#pragma unroll
                    for (int half = 0; half < 2; half++) {
                        int r = wm * 64 + mt * 16 + qr + half * 8;
                        int n = wn * 32 + nt * 8 + qc * 2;
                        stage_f[r * 132 + n]     = acc[mt][nt][half * 2];
                        stage_f[r * 132 + n + 1] = acc[mt][nt][half * 2 + 1];
                    }
            __syncthreads();

            const int j0 = n0 >> 2;
#pragma unroll
            for (int i = tid; i < 4096; i += 256) {
                int r  = i >> 5;
                int jj = i & 31;
                int b  = m0 + r;
                int j  = j0 + jj;
                float4 a4 = *(const float4*)&stage_f[r * 132 + jj * 4];
                float4 b4 = *(const float4*)(g_bias + n0 + jj * 4);
                float gi = a4.x + b4.x;
                float gf = a4.y + b4.y;
                float gg = a4.z + b4.z;
                float go = a4.w + b4.w;

                float i_ = 1.0f / (1.0f + expf(-gi));
                float f_ = 1.0f / (1.0f + expf(-gf));
                float g_ = tanhf(gg);
                float o_ = 1.0f / (1.0f + expf(-go));

                int idx = b * H_ + j;
                float c = f_ * g_c[idx] + i_ * g_;
                float h = o_ * tanhf(c);
                g_c[idx] = c;

                size_t oo = ((size_t)b * T_ + t) * H_ + j;
                out_hid[oo] = h;
                g_H[oo]     = __float2half_rn(h);
            }
            __syncthreads();   // stage_f free before next tile's loads
        }

        // ---- group barrier (skip after last step) ----
        if (t + 1 < T_) {
            if (tid == 0) {
                __threadfence();
                atomicAdd(&g_bar[grp], 1);
                while (*(volatile int*)&g_bar[grp] < GROUP_CTAS * (t + 1))
                    __nanosleep(64);
                __threadfence();
            }
            __syncthreads();
        }
    }
}

// ---------------------------------------------------------------------------
// probs GEMM: H @ Wgen^T, K=512 -> probs (+bg, n<97).  grid (1, 832).
// ---------------------------------------------------------------------------
__global__ void __launch_bounds__(256, 2)
probs_kernel(const float* __restrict__ bias, float* __restrict__ outp)
{
    extern __shared__ char dsm[];

    const int tid = threadIdx.x;
    const int wid = tid >> 5;
    const int lid = tid & 31;
    const int wm  = wid & 1;
    const int wn  = wid >> 1;
    const int m0  = blockIdx.y * 128;

    uint32_t raw  = smem_u32(dsm);
    uint32_t base = (raw + 127) & ~127u;
    uint32_t stg[NSTAGES];
#pragma unroll
    for (int s = 0; s < NSTAGES; s++) stg[s] = base + s * STAGE_BYTES;

    float acc[4][4][4];
#pragma unroll
    for (int mt = 0; mt < 4; mt++)
#pragma unroll
        for (int nt = 0; nt < 4; nt++)
#pragma unroll
            for (int r = 0; r < 4; r++) acc[mt][nt][r] = 0.0f;

    const int a_r  = lid & 15;
    const int a_kh = lid >> 4;
    const int b_r  = (lid & 7) + ((lid & 16) ? 8 : 0);
    const int b_kh = (lid >> 3) & 1;

    auto load_stage = [&](int ch, uint32_t sb) {
        const int k0 = ch * 64;
#pragma unroll
        for (int i = tid; i < 1024; i += 256) {
            int r = i >> 3, u = i & 7;
            uint32_t sw = (r << 7) + ((u ^ (r & 7)) << 4);
            cp16(sb + sw,              g_H  + (size_t)(m0 + r) * H_ + k0 + u * 8);
            cp16(sb + TILE_BYTES + sw, g_Wg + (size_t)r * H_ + k0 + u * 8);
        }
    };

    load_stage(0, stg[0]); cp_commit();
    load_stage(1, stg[1]); cp_commit();

    for (int ch = 0; ch < 8; ch++) {
        if (ch + 2 < 8) load_stage(ch + 2, stg[(ch + 2) % NSTAGES]);
        cp_commit();
        cp_wait<2>();
        __syncthreads();

        const uint32_t aA = stg[ch % NSTAGES];
        const uint32_t aB = aA + TILE_BYTES;
#pragma unroll
        for (int ks = 0; ks < 4; ks++) {
            uint32_t af[4][4], bf[2][4];
#pragma unroll
            for (int mt = 0; mt < 4; mt++) {
                int row = wm * 64 + mt * 16 + a_r;
                int kb  = ks * 2 + a_kh;
                ldmx4(af[mt], aA + (row << 7) + ((kb ^ (row & 7)) << 4));
            }
#pragma unroll
            for (int p = 0; p < 2; p++) {
                int row = wn * 32 + p * 16 + b_r;
                int kb  = ks * 2 + b_kh;
                ldmx4(bf[p], aB + (row << 7) + ((kb ^ (row & 7)) << 4));
            }
#pragma unroll
            for (int mt = 0; mt < 4; mt++)
#pragma unroll
                for (int nt = 0; nt < 4; nt++) {
                    int p = nt >> 1, o = (nt & 1) * 2;
                    mma_f16(acc[mt][nt], af[mt], bf[p][o], bf[p][o + 1]);
                }
        }
        __syncthreads();
    }

    const int qr = lid >> 2, qc = lid & 3;
#pragma unroll
    for (int mt = 0; mt < 4; mt++)
#pragma unroll
        for (int nt = 0; nt < 4; nt++)
#pragma unroll
            for (int half = 0; half < 2; half++) {
                int m = m0 + wm * 64 + mt * 16 + qr + half * 8;
                int n = wn * 32 + nt * 8 + qc * 2;
                float v0 = acc[mt][nt][half * 2];
                float v1 = acc[mt][nt][half * 2 + 1];
                if (n < NC_)     outp[(size_t)m * NC_ + n]     = v0 + bias[n];
                if (n + 1 < NC_) outp[(size_t)m * NC_ + n + 1] = v1 + bias[n + 1];
            }
}

// ---------------------------------------------------------------------------
// Launch: zero -> converts -> persistent recurrent (26 steps) -> probs
// d_out = [probs (B*T*97) | output_hiddens (B*T*512)]
// ---------------------------------------------------------------------------
extern "C" void kernel_launch(void* const* d_in, const int* in_sizes, int n_in,
                              void* d_out, int out_size)
{
    const float* bh   = (const float*)d_in[0];
    const int*   text = (const int*)  d_in[1];
    const float* emb  = (const float*)d_in[2];
    const float* Wih  = (const float*)d_in[3];
    const float* Whh  = (const float*)d_in[4];
    const float* bih  = (const float*)d_in[5];
    const float* bhh  = (const float*)d_in[6];
    const float* Wg   = (const float*)d_in[7];
    const float* bg   = (const float*)d_in[8];

    float* probs = (float*)d_out;                     // [M1, 97]
    float* hid   = probs + (size_t)M1_ * NC_;         // [M1, 512]

    (void)in_sizes; (void)n_in; (void)out_size;

    cudaFuncSetAttribute((const void*)recurrent_kernel,
                         cudaFuncAttributeMaxDynamicSharedMemorySize, SMEM_DYN);
    cudaFuncSetAttribute((const void*)probs_kernel,
                         cudaFuncAttributeMaxDynamicSharedMemorySize, SMEM_DYN);

    zero_state_kernel<<<(B_ * H_ / 4) / 256, 256>>>();
    convert_x_kernel<<<M1_, K1_ / 4>>>(bh, text, emb);
    convert_w_kernel<<<G_, KC_ / 4>>>(Whh, Wih);
    convert_wg_kernel<<<128, H_ / 4>>>(Wg);
    bias_kernel<<<8, 256>>>(bih, bhh);

    recurrent_kernel<<<GROUPS * GROUP_CTAS, 256, SMEM_DYN>>>(hid);

    probs_kernel<<<dim3(1, 832), 256, SMEM_DYN>>>(bg, probs);
}

// round 14
// speedup vs baseline: 1.0732x; 1.0165x over previous
#include <cuda_runtime.h>
#include <cuda_fp16.h>
#include <stdint.h>
#include <math.h>

// Problem constants
#define B_   4096
#define T_   26
#define IN_  512
#define H_   512
#define NC_  97
#define NE_  256
#define K1_  (IN_ + NE_)   // 768  (x = concat(batch_H, emb))
#define KC_  (H_ + K1_)    // 1280 (combined [h | x] contraction)
#define G_   (4 * H_)      // 2048
#define M1_  (B_ * T_)     // 106496

// Recurrent kernel: A tile 128x(64k) = 16KB, B tile 256x(64k) = 32KB
#define TILE_A      16384
#define TILE_B      32768
#define RSTAGE      (TILE_A + TILE_B)        // 49152
#define NSTAGES     3
#define SMEM_REC    (NSTAGES * RSTAGE + 128) // 147584 (occ 1)

// probs kernel keeps the old 128x128 shape (2x16KB stages)
#define PTILE       16384
#define PSTAGE      (2 * PTILE)
#define SMEM_PROBS  (NSTAGES * PSTAGE + 128)

// Persistent decomposition: 32 groups x 4 CTAs = 128 CTAs (<=148, occ 1)
#define GROUPS      32
#define GROUP_CTAS  4      // each CTA owns 512 n-cols = 2 passes of 256

// ---------------------------------------------------------------------------
// Scratch (device globals: no allocation allowed anywhere)
// ---------------------------------------------------------------------------
__device__ float g_c[B_ * H_];                    // cell state
__device__ __half g_x[(size_t)M1_ * K1_];         // concat(batch_H, emb) fp16
__device__ __half g_H[(size_t)M1_ * H_];          // hiddens fp16 [b*T+t, H]
__device__ __half g_W[G_ * KC_];                  // [Whh | Wih] fp16, gate-permuted
__device__ __half g_Wg[128 * H_];                 // W_gen padded to 128 rows
__device__ float g_bias[G_];                      // bih+bhh, PERMUTED gate order
__device__ int   g_bar[GROUPS];                   // per-group arrival counters

// ---------------------------------------------------------------------------
// PTX helpers (compute_103-safe: ldmatrix + mma.sync + cp.async)
// ---------------------------------------------------------------------------
__device__ __forceinline__ uint32_t smem_u32(const void* p) {
    uint32_t a;
    asm("{ .reg .u64 t; cvta.to.shared.u64 t, %1; cvt.u32.u64 %0, t; }"
        : "=r"(a) : "l"(p));
    return a;
}

__device__ __forceinline__ void ldmx4(uint32_t* r, uint32_t addr) {
    asm volatile("ldmatrix.sync.aligned.m8n8.x4.shared.b16 {%0,%1,%2,%3}, [%4];"
                 : "=r"(r[0]), "=r"(r[1]), "=r"(r[2]), "=r"(r[3]) : "r"(addr));
}

__device__ __forceinline__ void mma_f16(float* d, const uint32_t* a,
                                        uint32_t b0, uint32_t b1) {
    asm volatile(
        "mma.sync.aligned.m16n8k16.row.col.f32.f16.f16.f32 "
        "{%0,%1,%2,%3}, {%4,%5,%6,%7}, {%8,%9}, {%0,%1,%2,%3};"
        : "+f"(d[0]), "+f"(d[1]), "+f"(d[2]), "+f"(d[3])
        : "r"(a[0]), "r"(a[1]), "r"(a[2]), "r"(a[3]), "r"(b0), "r"(b1));
}

__device__ __forceinline__ void cp16(uint32_t s, const void* g) {
    asm volatile("cp.async.cg.shared.global [%0], [%1], 16;"
                 :: "r"(s), "l"(g) : "memory");
}
__device__ __forceinline__ void cp_commit() {
    asm volatile("cp.async.commit_group;" ::: "memory");
}
template <int N>
__device__ __forceinline__ void cp_wait() {
    asm volatile("cp.async.wait_group %0;" :: "n"(N) : "memory");
}

// fast pointwise (error ~2^-21; inf-safe)
__device__ __forceinline__ float fsig(float x) {
    return __fdividef(1.0f, 1.0f + __expf(-x));
}
__device__ __forceinline__ float ftanh(float x) {
    return 1.0f - __fdividef(2.0f, __expf(2.0f * x) + 1.0f);
}

// ---------------------------------------------------------------------------
// Small prep kernels
// ---------------------------------------------------------------------------
__global__ void zero_state_kernel() {
    int i = blockIdx.x * blockDim.x + threadIdx.x;
    ((float4*)g_c)[i] = make_float4(0.f, 0.f, 0.f, 0.f);
    if (blockIdx.x == 0 && threadIdx.x < GROUPS) g_bar[threadIdx.x] = 0;
}

// x = concat(batch_H, emb[text]) -> fp16.  grid = M1, block = 192
__global__ void convert_x_kernel(const float* __restrict__ bh,
                                 const int* __restrict__ text,
                                 const float* __restrict__ emb) {
    int m = blockIdx.x;
    int k = threadIdx.x * 4;
    float4 v;
    if (k < IN_) v = *(const float4*)(bh + (size_t)m * IN_ + k);
    else         v = *(const float4*)(emb + (size_t)text[m] * NE_ + (k - IN_));
    size_t o = (size_t)m * K1_ + k;
    g_x[o]   = __float2half_rn(v.x);
    g_x[o+1] = __float2half_rn(v.y);
    g_x[o+2] = __float2half_rn(v.z);
    g_x[o+3] = __float2half_rn(v.w);
}

// Combined weight [Whh | Wih], gate-permuted rows -> fp16.  grid = G_, block = 320
__global__ void convert_w_kernel(const float* __restrict__ Whh,
                                 const float* __restrict__ Wih) {
    int r = blockIdx.x;
    int k = threadIdx.x * 4;
    int sr = (r & 3) * H_ + (r >> 2);         // gate permutation
    float4 v;
    if (k < H_) v = *(const float4*)(Whh + (size_t)sr * H_ + k);
    else        v = *(const float4*)(Wih + (size_t)sr * K1_ + (k - H_));
    size_t o = (size_t)r * KC_ + k;
    g_W[o]   = __float2half_rn(v.x);
    g_W[o+1] = __float2half_rn(v.y);
    g_W[o+2] = __float2half_rn(v.z);
    g_W[o+3] = __float2half_rn(v.w);
}

// W_gen (padded to 128 rows) -> fp16.  grid = 128, block = 128
__global__ void convert_wg_kernel(const float* __restrict__ Wg) {
    int r = blockIdx.x;
    int k = threadIdx.x * 4;
    float4 v = make_float4(0.f, 0.f, 0.f, 0.f);
    if (r < NC_) v = *(const float4*)(Wg + (size_t)r * H_ + k);
    size_t o = (size_t)r * H_ + k;
    g_Wg[o]   = __float2half_rn(v.x);
    g_Wg[o+1] = __float2half_rn(v.y);
    g_Wg[o+2] = __float2half_rn(v.z);
    g_Wg[o+3] = __float2half_rn(v.w);
}

// g_bias[n] = bih[perm(n)] + bhh[perm(n)].  grid = 8, block = 256
__global__ void bias_kernel(const float* __restrict__ bih,
                            const float* __restrict__ bhh) {
    int n = blockIdx.x * blockDim.x + threadIdx.x;
    int sr = (n & 3) * H_ + (n >> 2);
    g_bias[n] = bih[sr] + bhh[sr];
}

// ---------------------------------------------------------------------------
// Persistent recurrent kernel: 128 CTAs = 32 groups x 4, occ 1.
// Group g owns batch rows [g*128, g*128+128); CTA sub owns n-cols
// [sub*512, sub*512+512) as 2 passes of 256.  Warp tile 64x64 (8 warps).
// gates_t = [h_{t-1} | x_t] @ [Whh | Wih]^T, K = 1280 (20 chunks of 64).
// t=0 starts at chunk 8 (h = 0).  Per-group atomic barrier between steps.
// ---------------------------------------------------------------------------
__global__ void __launch_bounds__(256, 1)
recurrent_kernel(float* __restrict__ out_hid)
{
    extern __shared__ char dsm[];

    const int tid = threadIdx.x;
    const int wid = tid >> 5;
    const int lid = tid & 31;
    const int wm  = wid & 1;    // 2 m-blocks of 64
    const int wn  = wid >> 1;   // 4 n-blocks of 64
    const int grp = blockIdx.x >> 2;
    const int sub = blockIdx.x & 3;
    const int m0  = grp * 128;

    uint32_t raw  = smem_u32(dsm);
    uint32_t base = (raw + 127) & ~127u;
    float* stage_f = (float*)(dsm + (base - raw));   // 128x132 f32 (epilogue)
    uint32_t stg[NSTAGES];
#pragma unroll
    for (int s = 0; s < NSTAGES; s++) stg[s] = base + s * RSTAGE;

    const int a_r  = lid & 15;
    const int a_kh = lid >> 4;
    const int b_r  = (lid & 7) + ((lid & 16) ? 8 : 0);
    const int b_kh = (lid >> 3) & 1;
    const int qr = lid >> 2, qc = lid & 3;

    for (int t = 0; t < T_; t++) {
        const __half* Ah = g_H + (size_t)(t - 1) * H_;  // row b -> (b*T+t-1)*H
        const __half* Ax = g_x + (size_t)t * K1_;       // row b -> (b*T+t)*K1
        const int start = (t == 0) ? 8 : 0;             // t=0: h part is zero

#pragma unroll 1
        for (int pass = 0; pass < 2; pass++) {
            const int np = sub * 512 + pass * 256;      // 256 n-cols this pass

            float acc[4][8][4];
#pragma unroll
            for (int mt = 0; mt < 4; mt++)
#pragma unroll
                for (int nt = 0; nt < 8; nt++)
#pragma unroll
                    for (int r = 0; r < 4; r++) acc[mt][nt][r] = 0.0f;

            // chunk ch: 0..7 -> h(t-1), 8..19 -> x(t)
            auto load_stage = [&](int ch, uint32_t sb) {
                // A: 128 rows x 128B
#pragma unroll
                for (int i = tid; i < 1024; i += 256) {
                    int r = i >> 3, u = i & 7;
                    uint32_t sw = (r << 7) + ((u ^ (r & 7)) << 4);
                    const __half* src = (ch < 8)
                        ? Ah + ((size_t)(m0 + r) * T_) * H_ + ch * 64 + u * 8
                        : Ax + ((size_t)(m0 + r) * T_) * K1_ + (ch - 8) * 64 + u * 8;
                    cp16(sb + sw, src);
                }
                // B: 256 rows x 128B
#pragma unroll
                for (int i = tid; i < 2048; i += 256) {
                    int r = i >> 3, u = i & 7;
                    uint32_t sw = (r << 7) + ((u ^ (r & 7)) << 4);
                    cp16(sb + TILE_A + sw,
                         g_W + (size_t)(np + r) * KC_ + ch * 64 + u * 8);
                }
            };

            load_stage(start, stg[start % NSTAGES]);           cp_commit();
            load_stage(start + 1, stg[(start + 1) % NSTAGES]); cp_commit();

            for (int ch = start; ch < 20; ch++) {
                if (ch + 2 < 20) load_stage(ch + 2, stg[(ch + 2) % NSTAGES]);
                cp_commit();
                cp_wait<2>();
                __syncthreads();

                const uint32_t aA = stg[ch % NSTAGES];
                const uint32_t aB = aA + TILE_A;
#pragma unroll
                for (int ks = 0; ks < 4; ks++) {
                    uint32_t af[4][4], bf[4][4];
#pragma unroll
                    for (int mt = 0; mt < 4; mt++) {
                        int row = wm * 64 + mt * 16 + a_r;
                        int kb  = ks * 2 + a_kh;
                        ldmx4(af[mt], aA + (row << 7) + ((kb ^ (row & 7)) << 4));
                    }
#pragma unroll
                    for (int p = 0; p < 4; p++) {
                        int row = wn * 64 + p * 16 + b_r;
                        int kb  = ks * 2 + b_kh;
                        ldmx4(bf[p], aB + (row << 7) + ((kb ^ (row & 7)) << 4));
                    }
#pragma unroll
                    for (int mt = 0; mt < 4; mt++)
#pragma unroll
                        for (int nt = 0; nt < 8; nt++) {
                            int p = nt >> 1, o = (nt & 1) * 2;
                            mma_f16(acc[mt][nt], af[mt], bf[p][o], bf[p][o + 1]);
                        }
                }
                __syncthreads();
            }
            cp_wait<0>();
            __syncthreads();   // all async writes done before stage_f reuse

            // ---- epilogue in two 128-col halves ----
#pragma unroll 1
            for (int hf = 0; hf < 2; hf++) {
                if ((wn >> 1) == hf) {
#pragma unroll
                    for (int mt = 0; mt < 4; mt++)
#pragma unroll
                        for (int nt = 0; nt < 8; nt++)
#pragma unroll
                            for (int half = 0; half < 2; half++) {
                                int r = wm * 64 + mt * 16 + qr + half * 8;
                                int n = (wn & 1) * 64 + nt * 8 + qc * 2;
                                stage_f[r * 132 + n]     = acc[mt][nt][half * 2];
                                stage_f[r * 132 + n + 1] = acc[mt][nt][half * 2 + 1];
                            }
                }
                __syncthreads();

                const int nb = np + hf * 128;   // global n-col base
                const int j0 = nb >> 2;         // first hidden unit
#pragma unroll
                for (int i = tid; i < 4096; i += 256) {
                    int r  = i >> 5;
                    int jj = i & 31;
                    int b  = m0 + r;
                    int j  = j0 + jj;
                    float4 a4 = *(const float4*)&stage_f[r * 132 + jj * 4];
                    float4 b4 = *(const float4*)(g_bias + nb + jj * 4);

                    float i_ = fsig(a4.x + b4.x);
                    float f_ = fsig(a4.y + b4.y);
                    float g_ = ftanh(a4.z + b4.z);
                    float o_ = fsig(a4.w + b4.w);

                    int idx = b * H_ + j;
                    float c = f_ * g_c[idx] + i_ * g_;
                    float h = o_ * ftanh(c);
                    g_c[idx] = c;

                    size_t oo = ((size_t)b * T_ + t) * H_ + j;
                    out_hid[oo] = h;
                    g_H[oo]     = __float2half_rn(h);
                }
                __syncthreads();
            }
        }

        // ---- group barrier (skip after last step) ----
        if (t + 1 < T_) {
            if (tid == 0) {
                __threadfence();
                atomicAdd(&g_bar[grp], 1);
                while (*(volatile int*)&g_bar[grp] < GROUP_CTAS * (t + 1))
                    __nanosleep(64);
                __threadfence();
            }
            __syncthreads();
        }
    }
}

// ---------------------------------------------------------------------------
// probs GEMM: H @ Wgen^T, K=512 -> probs (+bg, n<97).  grid (1, 832), occ 2.
// ---------------------------------------------------------------------------
__global__ void __launch_bounds__(256, 2)
probs_kernel(const float* __restrict__ bias, float* __restrict__ outp)
{
    extern __shared__ char dsm[];

    const int tid = threadIdx.x;
    const int wid = tid >> 5;
    const int lid = tid & 31;
    const int wm  = wid & 1;
    const int wn  = wid >> 1;
    const int m0  = blockIdx.y * 128;

    uint32_t raw  = smem_u32(dsm);
    uint32_t base = (raw + 127) & ~127u;
    uint32_t stg[NSTAGES];
#pragma unroll
    for (int s = 0; s < NSTAGES; s++) stg[s] = base + s * PSTAGE;

    float acc[4][4][4];
#pragma unroll
    for (int mt = 0; mt < 4; mt++)
#pragma unroll
        for (int nt = 0; nt < 4; nt++)
#pragma unroll
            for (int r = 0; r < 4; r++) acc[mt][nt][r] = 0.0f;

    const int a_r  = lid & 15;
    const int a_kh = lid >> 4;
    const int b_r  = (lid & 7) + ((lid & 16) ? 8 : 0);
    const int b_kh = (lid >> 3) & 1;

    auto load_stage = [&](int ch, uint32_t sb) {
        const int k0 = ch * 64;
#pragma unroll
        for (int i = tid; i < 1024; i += 256) {
            int r = i >> 3, u = i & 7;
            uint32_t sw = (r << 7) + ((u ^ (r & 7)) << 4);
            cp16(sb + sw,         g_H  + (size_t)(m0 + r) * H_ + k0 + u * 8);
            cp16(sb + PTILE + sw, g_Wg + (size_t)r * H_ + k0 + u * 8);
        }
    };

    load_stage(0, stg[0]); cp_commit();
    load_stage(1, stg[1]); cp_commit();

    for (int ch = 0; ch < 8; ch++) {
        if (ch + 2 < 8) load_stage(ch + 2, stg[(ch + 2) % NSTAGES]);
        cp_commit();
        cp_wait<2>();
        __syncthreads();

        const uint32_t aA = stg[ch % NSTAGES];
        const uint32_t aB = aA + PTILE;
#pragma unroll
        for (int ks = 0; ks < 4; ks++) {
            uint32_t af[4][4], bf[2][4];
#pragma unroll
            for (int mt = 0; mt < 4; mt++) {
                int row = wm * 64 + mt * 16 + a_r;
                int kb  = ks * 2 + a_kh;
                ldmx4(af[mt], aA + (row << 7) + ((kb ^ (row & 7)) << 4));
            }
#pragma unroll
            for (int p = 0; p < 2; p++) {
                int row = wn * 32 + p * 16 + b_r;
                int kb  = ks * 2 + b_kh;
                ldmx4(bf[p], aB + (row << 7) + ((kb ^ (row & 7)) << 4));
            }
#pragma unroll
            for (int mt = 0; mt < 4; mt++)
#pragma unroll
                for (int nt = 0; nt < 4; nt++) {
                    int p = nt >> 1, o = (nt & 1) * 2;
                    mma_f16(acc[mt][nt], af[mt], bf[p][o], bf[p][o + 1]);
                }
        }
        __syncthreads();
    }

    const int qr = lid >> 2, qc = lid & 3;
#pragma unroll
    for (int mt = 0; mt < 4; mt++)
#pragma unroll
        for (int nt = 0; nt < 4; nt++)
#pragma unroll
            for (int half = 0; half < 2; half++) {
                int m = m0 + wm * 64 + mt * 16 + qr + half * 8;
                int n = wn * 32 + nt * 8 + qc * 2;
                float v0 = acc[mt][nt][half * 2];
                float v1 = acc[mt][nt][half * 2 + 1];
                if (n < NC_)     outp[(size_t)m * NC_ + n]     = v0 + bias[n];
                if (n + 1 < NC_) outp[(size_t)m * NC_ + n + 1] = v1 + bias[n + 1];
            }
}

// ---------------------------------------------------------------------------
// Launch: zero -> converts -> persistent recurrent (26 steps) -> probs
// d_out = [probs (B*T*97) | output_hiddens (B*T*512)]
// ---------------------------------------------------------------------------
extern "C" void kernel_launch(void* const* d_in, const int* in_sizes, int n_in,
                              void* d_out, int out_size)
{
    const float* bh   = (const float*)d_in[0];
    const int*   text = (const int*)  d_in[1];
    const float* emb  = (const float*)d_in[2];
    const float* Wih  = (const float*)d_in[3];
    const float* Whh  = (const float*)d_in[4];
    const float* bih  = (const float*)d_in[5];
    const float* bhh  = (const float*)d_in[6];
    const float* Wg   = (const float*)d_in[7];
    const float* bg   = (const float*)d_in[8];

    float* probs = (float*)d_out;                     // [M1, 97]
    float* hid   = probs + (size_t)M1_ * NC_;         // [M1, 512]

    (void)in_sizes; (void)n_in; (void)out_size;

    cudaFuncSetAttribute((const void*)recurrent_kernel,
                         cudaFuncAttributeMaxDynamicSharedMemorySize, SMEM_REC);
    cudaFuncSetAttribute((const void*)probs_kernel,
                         cudaFuncAttributeMaxDynamicSharedMemorySize, SMEM_PROBS);

    zero_state_kernel<<<(B_ * H_ / 4) / 256, 256>>>();
    convert_x_kernel<<<M1_, K1_ / 4>>>(bh, text, emb);
    convert_w_kernel<<<G_, KC_ / 4>>>(Whh, Wih);
    convert_wg_kernel<<<128, H_ / 4>>>(Wg);
    bias_kernel<<<8, 256>>>(bih, bhh);

    recurrent_kernel<<<GROUPS * GROUP_CTAS, 256, SMEM_REC>>>(hid);

    probs_kernel<<<dim3(1, 832), 256, SMEM_PROBS>>>(bg, probs);
}